// round 17
// baseline (speedup 1.0000x reference)
#include <cuda_runtime.h>
#include <cuda_bf16.h>
#include <cstdint>
#include <cstddef>

#define T_STEPS 256
#define BB      64
#define DD      1024
#define ND3     3072
#define TBTOT   (T_STEPS * BB)   // 16384

typedef unsigned long long ull;

// ---------------------------------------------------------------------------
// Device scratch
// ---------------------------------------------------------------------------
__device__ float          g_xprojT[(size_t)ND3 * TBTOT];   // [n][tb]
__device__ float          g_WhT  [(size_t)ND3 * DD];       // [n][k] fp32 (scan)
__device__ __nv_bfloat16  g_Ahi[(size_t)TBTOT * DD];       // ins split  [m][k]
__device__ __nv_bfloat16  g_Alo[(size_t)TBTOT * DD];
__device__ __nv_bfloat16  g_Bhi[(size_t)ND3 * DD];         // W_i^T split [n][k]
__device__ __nv_bfloat16  g_Blo[(size_t)ND3 * DD];
__device__ unsigned g_bar;
__device__ int      g_dones_is_byte;

// ---------------------------------------------------------------------------
// f32x2 helpers (scan)
// ---------------------------------------------------------------------------
__device__ __forceinline__ void fma2(ull& d, ull a, ull b) {
    asm("fma.rn.f32x2 %0, %1, %2, %0;" : "+l"(d) : "l"(a), "l"(b));
}
__device__ __forceinline__ float2 up2(ull v) {
    float2 f; asm("mov.b64 {%0, %1}, %2;" : "=f"(f.x), "=f"(f.y) : "l"(v)); return f;
}
__device__ __forceinline__ float sigmoidf_(float x) { return 1.0f / (1.0f + __expf(-x)); }

// cp.async helpers
__device__ __forceinline__ void cp_async8(uint32_t dst_smem, const void* src) {
    asm volatile("cp.async.ca.shared.global [%0], [%1], 8;" :: "r"(dst_smem), "l"(src));
}
__device__ __forceinline__ void cp_async16(uint32_t dst_smem, const void* src) {
    asm volatile("cp.async.cg.shared.global [%0], [%1], 16;" :: "r"(dst_smem), "l"(src));
}
__device__ __forceinline__ void cp_commit() { asm volatile("cp.async.commit_group;"); }
template<int N>
__device__ __forceinline__ void cp_wait() {
    asm volatile("cp.async.wait_group %0;" :: "n"(N));
}

// mma.sync helpers (proven R9)
__device__ __forceinline__ void ldsm4(uint32_t* f, uint32_t addr) {
    asm volatile("ldmatrix.sync.aligned.m8n8.x4.shared.b16 {%0,%1,%2,%3}, [%4];"
        : "=r"(f[0]), "=r"(f[1]), "=r"(f[2]), "=r"(f[3]) : "r"(addr));
}
__device__ __forceinline__ void mma16816(float* c, const uint32_t* a, const uint32_t* b) {
    asm volatile("mma.sync.aligned.m16n8k16.row.col.f32.bf16.bf16.f32 "
        "{%0,%1,%2,%3}, {%4,%5,%6,%7}, {%8,%9}, {%0,%1,%2,%3};"
        : "+f"(c[0]), "+f"(c[1]), "+f"(c[2]), "+f"(c[3])
        : "r"(a[0]), "r"(a[1]), "r"(a[2]), "r"(a[3]), "r"(b[0]), "r"(b[1]));
}

// ---------------------------------------------------------------------------
// probe dones dtype + reset grid barrier
// ---------------------------------------------------------------------------
__global__ void probe_dones(const unsigned* __restrict__ d) {
    __shared__ int any_big;
    if (threadIdx.x == 0) any_big = 0;
    __syncthreads();
    const int nwords = (T_STEPS * BB) / 4;
    int local = 0;
    for (int i = threadIdx.x; i < nwords; i += blockDim.x)
        if (d[i] > 1u) local = 1;
    if (local) any_big = 1;
    __syncthreads();
    if (threadIdx.x == 0) { g_dones_is_byte = any_big; g_bar = 0u; }
}

// ---------------------------------------------------------------------------
// transpose W_h [D,3D] -> g_WhT [3D,D] (fp32, scan)
// ---------------------------------------------------------------------------
__global__ void transpose_wh(const float* __restrict__ W) {
    __shared__ float tile[32][33];
    int n  = blockIdx.x * 32 + threadIdx.x;
    int k0 = blockIdx.y * 32;
#pragma unroll
    for (int i = threadIdx.y; i < 32; i += 8)
        tile[i][threadIdx.x] = W[(size_t)(k0 + i) * ND3 + n];
    __syncthreads();
    int k  = k0 + threadIdx.x;
    int n0 = blockIdx.x * 32;
#pragma unroll
    for (int i = threadIdx.y; i < 32; i += 8)
        g_WhT[(size_t)(n0 + i) * DD + k] = tile[threadIdx.x][i];
}

// ---------------------------------------------------------------------------
// split ins -> bf16 hi/lo [m][k]
// ---------------------------------------------------------------------------
__global__ void convert_A(const float* __restrict__ A) {
    size_t i = ((size_t)blockIdx.x * 256 + threadIdx.x) * 4;
    float4 v = *(const float4*)(A + i);
    __nv_bfloat16 h[4], l[4];
    float f[4] = {v.x, v.y, v.z, v.w};
#pragma unroll
    for (int q = 0; q < 4; q++) {
        h[q] = __float2bfloat16(f[q]);
        l[q] = __float2bfloat16(f[q] - __bfloat162float(h[q]));
    }
    *(ull*)(g_Ahi + i) = *(ull*)h;
    *(ull*)(g_Alo + i) = *(ull*)l;
}

// ---------------------------------------------------------------------------
// W_i [k][3D] -> g_Bhi/g_Blo [n][k] bf16 (transpose + split)
// ---------------------------------------------------------------------------
__global__ void convert_wi(const float* __restrict__ W) {
    __shared__ float tile[32][33];
    int n  = blockIdx.x * 32 + threadIdx.x;
    int k0 = blockIdx.y * 32;
#pragma unroll
    for (int i = threadIdx.y; i < 32; i += 8)
        tile[i][threadIdx.x] = W[(size_t)(k0 + i) * ND3 + n];
    __syncthreads();
    int k  = k0 + threadIdx.x;
    int n0 = blockIdx.x * 32;
#pragma unroll
    for (int i = threadIdx.y; i < 32; i += 8) {
        float x = tile[threadIdx.x][i];
        __nv_bfloat16 hi = __float2bfloat16(x);
        __nv_bfloat16 lo = __float2bfloat16(x - __bfloat162float(hi));
        g_Bhi[(size_t)(n0 + i) * DD + k] = hi;
        g_Blo[(size_t)(n0 + i) * DD + k] = lo;
    }
}

// ---------------------------------------------------------------------------
// HMMA bf16-split GEMM (proven R9 math), now 3-STAGE cp.async pipeline.
// g_xprojT[n][m] = (ins @ W_i)[m][n] + b_i[n]
// ---------------------------------------------------------------------------
#define GM_ARR_B   10240                   // 128 rows * 80B
#define GM_SET_B   (4 * GM_ARR_B)          // 40960
#define GM_DYN_B   (3 * GM_SET_B)          // 122880 (3 stages; epilogue Cs 67584 fits)

__global__ void __launch_bounds__(256) gemm_xproj_mma(const float* __restrict__ bias)
{
    extern __shared__ __align__(16) unsigned char dynsm[];
    const uint32_t sb = (uint32_t)__cvta_generic_to_shared(dynsm);

    const int tid  = threadIdx.x;
    const int lane = tid & 31;
    const int warp = tid >> 5;
    const int wm   = warp & 3;
    const int wn   = warp >> 2;
    const int n0   = blockIdx.x << 7;
    const int m0   = blockIdx.y << 7;

    float c[2][8][4];
#pragma unroll
    for (int mt = 0; mt < 2; mt++)
#pragma unroll
        for (int j = 0; j < 8; j++)
#pragma unroll
            for (int q = 0; q < 4; q++) c[mt][j][q] = 0.f;

    auto stage = [&](int kc) {
        const int kb = kc * 32;
        const uint32_t bo = sb + (kc % 3) * GM_SET_B;
#pragma unroll
        for (int i = 0; i < 8; i++) {
            int e = tid + (i << 8);
            int arr = e >> 9;
            int row = (e >> 2) & 127;
            int seg = e & 3;
            const __nv_bfloat16* gsrc;
            if      (arr == 0) gsrc = g_Ahi + (size_t)(m0 + row) * DD;
            else if (arr == 1) gsrc = g_Alo + (size_t)(m0 + row) * DD;
            else if (arr == 2) gsrc = g_Bhi + (size_t)(n0 + row) * DD;
            else               gsrc = g_Blo + (size_t)(n0 + row) * DD;
            cp_async16(bo + arr * GM_ARR_B + row * 80 + seg * 16, gsrc + kb + seg * 8);
        }
        cp_commit();
    };

    stage(0);
    stage(1);
    for (int kc = 0; kc < 32; kc++) {
        if (kc < 30)      { stage(kc + 2); cp_wait<2>(); }
        else if (kc == 30){ cp_wait<1>(); }
        else              { cp_wait<0>(); }
        __syncthreads();

        const uint32_t cur  = sb + (kc % 3) * GM_SET_B;
        const uint32_t aoffh = cur;
        const uint32_t aoffl = cur + GM_ARR_B;
        const uint32_t boffh = cur + 2 * GM_ARR_B;
        const uint32_t boffl = cur + 3 * GM_ARR_B;

#pragma unroll
        for (int ks = 0; ks < 2; ks++) {
            uint32_t ahi[2][4], alo[2][4];
#pragma unroll
            for (int mt = 0; mt < 2; mt++) {
                uint32_t rowb = (uint32_t)((wm * 32 + mt * 16 + (lane & 15)) * 80
                                           + ks * 32 + (lane >> 4) * 16);
                ldsm4(ahi[mt], aoffh + rowb);
                ldsm4(alo[mt], aoffl + rowb);
            }
#pragma unroll
            for (int g = 0; g < 4; g++) {
                uint32_t nrow = (uint32_t)(wn * 64 + g * 16 +
                                 ((lane & 7) | (((lane >> 4) & 1) << 3)));
                uint32_t rb = nrow * 80 + ks * 32 + ((lane >> 3) & 1) * 16;
                uint32_t bhi[4], blo[4];
                ldsm4(bhi, boffh + rb);
                ldsm4(blo, boffl + rb);
#pragma unroll
                for (int mt = 0; mt < 2; mt++) {
                    mma16816(c[mt][g * 2],     ahi[mt], bhi);
                    mma16816(c[mt][g * 2],     ahi[mt], blo);
                    mma16816(c[mt][g * 2],     alo[mt], bhi);
                    mma16816(c[mt][g * 2 + 1], ahi[mt], bhi + 2);
                    mma16816(c[mt][g * 2 + 1], ahi[mt], blo + 2);
                    mma16816(c[mt][g * 2 + 1], alo[mt], bhi + 2);
                }
            }
        }
        __syncthreads();
    }

    // epilogue: stage C transposed in smem Cs[n][m] (stride 132), then store
    float* Cs = (float*)dynsm;
#pragma unroll
    for (int mt = 0; mt < 2; mt++)
#pragma unroll
        for (int j = 0; j < 8; j++)
#pragma unroll
            for (int q = 0; q < 4; q++) {
                int mrow = wm * 32 + mt * 16 + (lane >> 2) + ((q >> 1) & 1) * 8;
                int ncol = wn * 64 + j * 8 + (lane & 3) * 2 + (q & 1);
                Cs[ncol * 132 + mrow] = c[mt][j][q];
            }
    __syncthreads();

    {
        int n  = tid >> 1;
        int mh = (tid & 1) * 64;
        float bv = __ldg(&bias[n0 + n]);
        float* dst = g_xprojT + (size_t)(n0 + n) * TBTOT + m0 + mh;
        const float* src = Cs + n * 132 + mh;
#pragma unroll
        for (int i = 0; i < 16; i++) {
            float4 v = *(const float4*)(src + i * 4);
            v.x += bv; v.y += bv; v.z += bv; v.w += bv;
            *(float4*)(dst + i * 4) = v;
        }
    }
}

// ---------------------------------------------------------------------------
// Persistent scan (R6/R9-proven, byte-identical): 128 CTAs x 512 threads
// ---------------------------------------------------------------------------
#define W_OFF    0
#define W_STRIDE 1032
#define HST_OFF  24768
#define HST_BUF  8320
#define PART_OFF 41408
#define PART_STRIDE 66
#define SOUT_OFF 54080
#define DONE_OFF 54656
#define SMEM_FLOATS 54720

__global__ void __launch_bounds__(512, 1) scan_kernel(
    const float* __restrict__ hiddens,
    const void*  __restrict__ dones_raw,
    const float* __restrict__ init_carry,
    const float* __restrict__ b_hn,
    float* __restrict__ out)
{
    extern __shared__ __align__(16) float sm[];
    float* wsm  = sm + W_OFF;
    float* hst  = sm + HST_OFF;
    float* part = sm + PART_OFF;
    float* sout = sm + SOUT_OFF;
    int*   sdone = (int*)(sm + DONE_OFF);

    const int tid  = threadIdx.x;
    const int c    = blockIdx.x;
    const int bgrp = tid & 7;
    const int jloc = (tid >> 3) & 7;
    const int s    = tid >> 6;
    const int sb   = tid >> 3;
    const int skq  = tid & 7;
    const int rb   = tid & 63;
    const int rjl  = tid >> 6;
    const int jr   = c * 8 + rjl;

    float* ys = out + (size_t)BB * DD;

#pragma unroll
    for (int i = 0; i < 12; i++) {
        int e = tid + i * 512;
        int row = e >> 8;
        int kq  = e & 255;
        int g = row >> 3, jl = row & 7;
        float4 v = *(const float4*)(g_WhT + (size_t)(g * DD + c * 8 + jl) * DD + kq * 4);
        *(float4*)(wsm + row * W_STRIDE + kq * 4) = v;
    }

    const float* w0p = wsm + (0 * 8 + jloc) * W_STRIDE;
    const float* w1p = wsm + (1 * 8 + jloc) * W_STRIDE;
    const float* w2p = wsm + (2 * 8 + jloc) * W_STRIDE;

    float hprev = init_carry[(size_t)rb * DD + jr];
    const float bhn_r = b_hn[jr];
    const int is_byte = g_dones_is_byte;
    const unsigned char* dones_b = (const unsigned char*)dones_raw;
    const int*           dones_i = (const int*)dones_raw;

    const uint32_t hst_base_u32 = (uint32_t)__cvta_generic_to_shared(hst);
    const uint32_t my_dst_off   = (uint32_t)((sb * 130 + skq * 2) * 4);

    __syncthreads();

    for (int t = 0; t < T_STEPS; t++) {
        if (tid < 64)
            sdone[tid] = is_byte ? (int)dones_b[t * 64 + tid]
                                 : (dones_i[t * 64 + tid] != 0);
        __syncthreads();

        const size_t tb = (size_t)t * 64 + rb;
        float xr = __ldcg(g_xprojT + (size_t)jr * TBTOT + tb);
        float xz = __ldcg(g_xprojT + (size_t)(DD + jr) * TBTOT + tb);
        float xn = __ldcg(g_xprojT + (size_t)(2 * DD + jr) * TBTOT + tb);
        float hcand = __ldcg(hiddens + (size_t)t * (BB * DD) + (size_t)rb * DD + jr);
        const int mydone = sdone[rb];

        const float* prevb = (t == 0) ? init_carry : ys + (size_t)(t - 1) * (BB * DD);
        const float* hidt  = hiddens + (size_t)t * (BB * DD);
        const float* srcrow = (sdone[sb] ? hidt : prevb) + (size_t)sb * DD;

        {
            uint32_t dst = hst_base_u32 + my_dst_off;
#pragma unroll
            for (int i = 0; i < 8; i++)
                cp_async8(dst + i * 64, srcrow + skq * 2 + 16 * i);
            cp_commit();
        }

        ull acc[3][8];
#pragma unroll
        for (int g = 0; g < 3; g++)
#pragma unroll
            for (int ii = 0; ii < 8; ii++) acc[g][ii] = 0ull;

        for (int chunk = 0; chunk < 8; chunk++) {
            __syncthreads();
            if (chunk < 7) {
                const int kb = (chunk + 1) << 7;
                uint32_t dst = hst_base_u32 + (uint32_t)(((chunk + 1) & 1) * HST_BUF * 4) + my_dst_off;
#pragma unroll
                for (int i = 0; i < 8; i++)
                    cp_async8(dst + i * 64, srcrow + kb + skq * 2 + 16 * i);
                cp_commit();
                cp_wait<1>();
            } else {
                cp_wait<0>();
            }
            __syncthreads();

            const float* buf = hst + (chunk & 1) * HST_BUF;
            const int kw = chunk << 7;
#pragma unroll
            for (int q = 0; q < 4; q++) {
                const int k0 = s * 4 + q * 32;
                ulonglong2 wr2 = *(const ulonglong2*)(w0p + kw + k0);
                ulonglong2 wz2 = *(const ulonglong2*)(w1p + kw + k0);
                ulonglong2 wn2 = *(const ulonglong2*)(w2p + kw + k0);
#pragma unroll
                for (int ii = 0; ii < 8; ii++) {
                    const float* hb = buf + (bgrp + 8 * ii) * 130 + k0;
                    ull h01 = *(const ull*)(hb);
                    ull h23 = *(const ull*)(hb + 2);
                    fma2(acc[0][ii], h01, wr2.x); fma2(acc[0][ii], h23, wr2.y);
                    fma2(acc[1][ii], h01, wz2.x); fma2(acc[1][ii], h23, wz2.y);
                    fma2(acc[2][ii], h01, wn2.x); fma2(acc[2][ii], h23, wn2.y);
                }
            }
        }

#pragma unroll
        for (int g = 0; g < 3; g++)
#pragma unroll
            for (int ii = 0; ii < 8; ii++) {
                float2 p = up2(acc[g][ii]);
                part[((s * 3 + g) * 8 + jloc) * PART_STRIDE + (bgrp + 8 * ii)] = p.x + p.y;
            }
        __syncthreads();

        float sr = 0.f, szv = 0.f, snv = 0.f;
#pragma unroll
        for (int ss = 0; ss < 8; ss++) {
            sr  += part[((ss * 3 + 0) * 8 + rjl) * PART_STRIDE + rb];
            szv += part[((ss * 3 + 1) * 8 + rjl) * PART_STRIDE + rb];
            snv += part[((ss * 3 + 2) * 8 + rjl) * PART_STRIDE + rb];
        }
        float hself = mydone ? hcand : hprev;
        float r  = sigmoidf_(xr + sr);
        float z  = sigmoidf_(xz + szv);
        float nn = tanhf(xn + r * (snv + bhn_r));
        float hn = (1.0f - z) * nn + z * hself;
        hprev = hn;

        sout[rb * 9 + rjl] = hn;
        __syncthreads();
        {
            int b = tid >> 3, jl = tid & 7;
            float v = sout[b * 9 + jl];
            ys[((size_t)t * 64 + b) * DD + c * 8 + jl] = v;
            if (t == T_STEPS - 1) out[(size_t)b * DD + c * 8 + jl] = v;
        }
        __syncthreads();
        if (tid == 0) {
            __threadfence();
            atomicAdd(&g_bar, 1u);
            unsigned target = (unsigned)(t + 1) * 128u;
            while (*(volatile unsigned*)&g_bar < target) { }
            __threadfence();
        }
        __syncthreads();
    }
}

// ---------------------------------------------------------------------------
// Launch
// ---------------------------------------------------------------------------
extern "C" void kernel_launch(void* const* d_in, const int* in_sizes, int n_in,
                              void* d_out, int out_size) {
    (void)in_sizes; (void)n_in; (void)out_size;
    const float* ins        = (const float*)d_in[0];
    const float* hiddens    = (const float*)d_in[1];
    const void*  dones      = d_in[2];
    const float* init_carry = (const float*)d_in[3];
    const float* W_i        = (const float*)d_in[4];
    const float* W_h        = (const float*)d_in[5];
    const float* b_i        = (const float*)d_in[6];
    const float* b_hn       = (const float*)d_in[7];
    float* out = (float*)d_out;

    static int attr_set = 0;
    if (!attr_set) {
        cudaFuncSetAttribute(scan_kernel, cudaFuncAttributeMaxDynamicSharedMemorySize,
                             SMEM_FLOATS * 4);
        cudaFuncSetAttribute(gemm_xproj_mma, cudaFuncAttributeMaxDynamicSharedMemorySize,
                             GM_DYN_B);
        attr_set = 1;
    }

    probe_dones<<<1, 256>>>((const unsigned*)dones);
    transpose_wh<<<dim3(ND3 / 32, DD / 32), dim3(32, 8)>>>(W_h);
    convert_A<<<(TBTOT * DD) / (256 * 4), 256>>>(ins);
    convert_wi<<<dim3(ND3 / 32, DD / 32), dim3(32, 8)>>>(W_i);
    gemm_xproj_mma<<<dim3(ND3 / 128, TBTOT / 128), 256, GM_DYN_B>>>(b_i);
    scan_kernel<<<128, 512, SMEM_FLOATS * 4>>>(hiddens, dones, init_carry, b_hn, out);
}